// round 16
// baseline (speedup 1.0000x reference)
#include <cuda_runtime.h>
#include <cuda_fp16.h>
#include <cstdint>

// SNNModel: 3-layer LIF SNN, T=10. B=1024, D=4000, H=2048, O=1000.
// R16: persistent pipelined kernel (R15) + fp16-accumulate probe on the lo-split
// halves of L2/L3 (s·wl terms, |wl|~2^-11·|W|), folded to fp32 every ks (16-K)
// step so rounding stays ~1e-6. Hi halves remain fp32-accumulate. Precompute:
// pad_w1 folded into build_w1, flag init folded into build_xcat.
//   L1: x=xh+xl, W1=wh+wl; terms xh*wh, xh*wl, xl*wh; K'=1216/step.
//   L2/L3: spikes exact in fp16; W = Wh|Wl K-concat (K'=4096/step).

namespace {
constexpr int kB = 1024, kD = 4000, kH = 2048, kO = 1000, kT = 10;
constexpr int kK1  = 1216;          // L1 per-step K' (3*400 + 16 pad) = 19 chunks
constexpr int kLd1 = kT * kK1;      // 12160
constexpr int kNC1 = kLd1 / 64;     // 190
constexpr int kK2  = 2 * kH;        // 4096
constexpr int kNC23 = kT * 64;      // 640 chunks per L2/L3 CTA
constexpr unsigned kSmem = 3u * (64u * 128u + 16384u);   // 73728
}

// ---------------- persistent device buffers ----------------
__device__ __align__(16) __half g_s1all[(size_t)kT * kB * kH];
__device__ __align__(16) __half g_s2all[(size_t)kT * kB * kH];
__device__ __align__(16) __half g_A1c[(size_t)kB * kLd1];
__device__ __align__(16) __half g_W1c[(size_t)kH * kLd1];
__device__ __align__(16) __half g_W2c[(size_t)kH * kK2];
__device__ __align__(16) __half g_W3c[(size_t)1024 * kK2];
__device__ int g_flag1[kT];   // s1(t) complete: 256 arrivals
__device__ int g_flag2[kT];   // s2(t) complete: 256 arrivals

// ---------------- PTX helpers ----------------
__device__ __forceinline__ uint32_t smem_u32(const void* p) {
    uint32_t a;
    asm("{ .reg .u64 t; cvta.to.shared.u64 t, %1; cvt.u32.u64 %0, t; }" : "=r"(a) : "l"(p));
    return a;
}
__device__ __forceinline__ void cp16(uint32_t dst, const void* src) {
    asm volatile("cp.async.cg.shared.global [%0], [%1], 16;" :: "r"(dst), "l"(src));
}
__device__ __forceinline__ void cp_commit() { asm volatile("cp.async.commit_group;" ::: "memory"); }
__device__ __forceinline__ void cp_wait1()  { asm volatile("cp.async.wait_group 1;" ::: "memory"); }
__device__ __forceinline__ void cp_wait0()  { asm volatile("cp.async.wait_group 0;" ::: "memory"); }
__device__ __forceinline__ void ldmx4(uint32_t& r0, uint32_t& r1, uint32_t& r2, uint32_t& r3,
                                      uint32_t addr) {
    asm volatile("ldmatrix.sync.aligned.m8n8.x4.shared.b16 {%0,%1,%2,%3}, [%4];"
                 : "=r"(r0), "=r"(r1), "=r"(r2), "=r"(r3) : "r"(addr));
}
__device__ __forceinline__ void mma16816(float& c0, float& c1, float& c2, float& c3,
                                         uint32_t a0, uint32_t a1, uint32_t a2, uint32_t a3,
                                         uint32_t b0, uint32_t b1) {
    asm volatile(
        "mma.sync.aligned.m16n8k16.row.col.f32.f16.f16.f32 "
        "{%0,%1,%2,%3}, {%4,%5,%6,%7}, {%8,%9}, {%0,%1,%2,%3};"
        : "+f"(c0), "+f"(c1), "+f"(c2), "+f"(c3)
        : "r"(a0), "r"(a1), "r"(a2), "r"(a3), "r"(b0), "r"(b1));
}
__device__ __forceinline__ void mma16816h(uint32_t& c0, uint32_t& c1,
                                          uint32_t a0, uint32_t a1, uint32_t a2, uint32_t a3,
                                          uint32_t b0, uint32_t b1) {
    asm volatile(
        "mma.sync.aligned.m16n8k16.row.col.f16.f16.f16.f16 "
        "{%0,%1}, {%2,%3,%4,%5}, {%6,%7}, {%0,%1};"
        : "+r"(c0), "+r"(c1)
        : "r"(a0), "r"(a1), "r"(a2), "r"(a3), "r"(b0), "r"(b1));
}
__device__ __forceinline__ uint32_t sw128(uint32_t off) {
    return off ^ ((off >> 3) & 0x70);
}
__device__ __forceinline__ void wait_flag(volatile int* f, int target) {
    while (*f < target) __nanosleep(64);
    __threadfence();   // acquire
}

// ---------------- precompute kernels ----------------
// A1c[m, t*1216 + j] : [xh(400) | xh(400) | xl(400) | pad16]; block 0 zeroes flags.
__global__ void build_xcat(const float* __restrict__ x) {
    if (blockIdx.x == 0 && threadIdx.x < kT) {
        g_flag1[threadIdx.x] = 0; g_flag2[threadIdx.x] = 0;
    }
    long idx = (long)blockIdx.x * blockDim.x + threadIdx.x;
    if (idx >= (long)kB * kLd1) return;
    int m = (int)(idx / kLd1), c = (int)(idx % kLd1);
    int t = c / kK1, j = c % kK1;
    __half o = __float2half_rn(0.0f);
    if (j < 1200) {
        int seg = j / 400, kk = j % 400;
        float xv = x[(long)m * kD + t * 400 + kk];
        __half h = __float2half_rn(xv);
        o = (seg < 2) ? h : __float2half_rn(xv - __half2float(h));
    }
    g_A1c[idx] = o;
}

// W1c per step block: [wh(400) | wl(400) | wh(400) | pad16]; pad zeroed here too.
__global__ void build_w1(const float* __restrict__ W) {   // W: [4000, 2048]
    __shared__ float tile[32][33];
    int k0 = blockIdx.x * 32, n0 = blockIdx.y * 32;
    int tx = threadIdx.x & 31, ty = threadIdx.x >> 5;
    for (int i = 0; i < 32; i += 8)
        tile[ty + i][tx] = W[(long)(k0 + ty + i) * kH + n0 + tx];
    __syncthreads();
    for (int i = 0; i < 32; i += 8) {
        int n = n0 + ty + i, kg = k0 + tx;
        int t = kg / 400, kk = kg % 400;
        float v = tile[tx][ty + i];
        __half h = __float2half_rn(v);
        __half l = __float2half_rn(v - __half2float(h));
        long base = (long)n * kLd1 + (long)t * kK1;
        g_W1c[base + kk]       = h;
        g_W1c[base + 400 + kk] = l;
        g_W1c[base + 800 + kk] = h;
        if (kk >= 384)   // exactly 16 threads per (n, t): cover pad cols [1200,1216)
            g_W1c[base + 1200 + (kk - 384)] = __float2half_rn(0.0f);
    }
}

__global__ void build_w2(const float* __restrict__ W) {   // [2048,2048] -> [2048, 4096]
    __shared__ float tile[32][33];
    int k0 = blockIdx.x * 32, n0 = blockIdx.y * 32;
    int tx = threadIdx.x & 31, ty = threadIdx.x >> 5;
    for (int i = 0; i < 32; i += 8)
        tile[ty + i][tx] = W[(long)(k0 + ty + i) * kH + n0 + tx];
    __syncthreads();
    for (int i = 0; i < 32; i += 8) {
        int n = n0 + ty + i, k = k0 + tx;
        float v = tile[tx][ty + i];
        __half h = __float2half_rn(v);
        __half l = __float2half_rn(v - __half2float(h));
        long base = (long)n * kK2;
        g_W2c[base + k] = h; g_W2c[base + kH + k] = l;
    }
}

__global__ void build_w3(const float* __restrict__ W) {   // [2048,1000] -> [1024, 4096]
    __shared__ float tile[32][33];
    int k0 = blockIdx.x * 32, n0 = blockIdx.y * 32;
    int tx = threadIdx.x & 31, ty = threadIdx.x >> 5;
    for (int i = 0; i < 32; i += 8) {
        int n = n0 + tx;
        tile[ty + i][tx] = (n < kO) ? W[(long)(k0 + ty + i) * kO + n] : 0.0f;
    }
    __syncthreads();
    for (int i = 0; i < 32; i += 8) {
        int n = n0 + ty + i, k = k0 + tx;
        float v = tile[tx][ty + i];
        __half h = __float2half_rn(v);
        __half l = __float2half_rn(v - __half2float(h));
        long base = (long)n * kK2;
        g_W3c[base + k] = h; g_W3c[base + kH + k] = l;
    }
}

// ---------------- role bodies ----------------
struct Lane {
    int tid, wid, lid, wm, wn, g, tg, a_r, a_k, b_r, b_k;
};
__device__ __forceinline__ Lane mk_lane() {
    Lane L;
    L.tid = threadIdx.x; L.wid = L.tid >> 5; L.lid = L.tid & 31;
    L.wm = (L.wid >> 2) * 32; L.wn = (L.wid & 3) * 32;
    L.g = L.lid >> 2; L.tg = L.lid & 3;
    L.a_r = (L.lid & 7) + ((L.lid >> 3) & 1) * 8; L.a_k = (L.lid >> 4) * 16;
    L.b_r = (L.lid & 7) + (L.lid >> 4) * 8;       L.b_k = ((L.lid >> 3) & 1) * 16;
    return L;
}

// L1: 190 chunks, fp32 accumulate, LIF at c%19==18, arrive g_flag1.
__device__ __forceinline__ void run_l1(uint32_t sbase, int m0, int n0,
                                       const float* __restrict__ bias) {
    constexpr uint32_t kABytes = 64 * 128, kStage = kABytes + 16384;
    const Lane L = mk_lane();

    float accf[2][4][4], v1[2][4][4];
#pragma unroll
    for (int i = 0; i < 2; i++)
#pragma unroll
        for (int j = 0; j < 4; j++)
#pragma unroll
            for (int q = 0; q < 4; q++) { accf[i][j][q] = 0.0f; v1[i][j][q] = 0.0f; }

    float bv[4][2];
#pragma unroll
    for (int ni = 0; ni < 4; ni++) {
        int col = n0 + L.wn + ni * 8 + L.tg * 2;
        bv[ni][0] = bias[col]; bv[ni][1] = bias[col + 1];
    }

    auto load_chunk = [&](int c, int b) {
        const int k0 = c * 64;
        const uint32_t abuf = sbase + (uint32_t)b * kStage, wbuf = abuf + kABytes;
#pragma unroll
        for (int p = 0; p < 2; p++) {
            int off = (p * 256 + L.tid) * 16;
            cp16(abuf + sw128((uint32_t)off),
                 g_A1c + (long)(m0 + (off >> 7)) * kLd1 + k0 + ((off & 127) >> 1));
        }
#pragma unroll
        for (int p = 0; p < 4; p++) {
            int off = (p * 256 + L.tid) * 16;
            cp16(wbuf + sw128((uint32_t)off),
                 g_W1c + (long)(n0 + (off >> 7)) * kLd1 + k0 + ((off & 127) >> 1));
        }
        cp_commit();
    };

    load_chunk(0, 0); load_chunk(1, 1);

    for (int c = 0; c < kNC1; c++) {
        const int b = c % 3;
        if (c + 1 < kNC1) cp_wait1(); else cp_wait0();
        __syncthreads();
        if (c + 2 < kNC1) load_chunk(c + 2, (c + 2) % 3);

        const uint32_t abuf = sbase + (uint32_t)b * kStage, wbuf = abuf + kABytes;
#pragma unroll
        for (int ks = 0; ks < 4; ks++) {
            uint32_t af[2][4], bfr[2][4];
#pragma unroll
            for (int mi = 0; mi < 2; mi++) {
                uint32_t off = (uint32_t)((L.wm + mi * 16 + L.a_r) * 128 + ks * 32 + L.a_k);
                ldmx4(af[mi][0], af[mi][1], af[mi][2], af[mi][3], abuf + sw128(off));
            }
#pragma unroll
            for (int np = 0; np < 2; np++) {
                uint32_t off = (uint32_t)((L.wn + np * 16 + L.b_r) * 128 + ks * 32 + L.b_k);
                ldmx4(bfr[np][0], bfr[np][1], bfr[np][2], bfr[np][3], wbuf + sw128(off));
            }
#pragma unroll
            for (int mi = 0; mi < 2; mi++)
#pragma unroll
                for (int ni = 0; ni < 4; ni++) {
                    const uint32_t* bp = &bfr[ni >> 1][(ni & 1) * 2];
                    mma16816(accf[mi][ni][0], accf[mi][ni][1], accf[mi][ni][2], accf[mi][ni][3],
                             af[mi][0], af[mi][1], af[mi][2], af[mi][3], bp[0], bp[1]);
                }
        }

        if (c % 19 == 18) {
            const int st = c / 19;
            __half* sout = g_s1all + (size_t)st * kB * kH;
#pragma unroll
            for (int mi = 0; mi < 2; mi++) {
                int row0 = m0 + L.wm + mi * 16 + L.g;
#pragma unroll
                for (int ni = 0; ni < 4; ni++) {
                    int col = n0 + L.wn + ni * 8 + L.tg * 2;
                    float s[4];
#pragma unroll
                    for (int q = 0; q < 4; q++) {
                        float cc = accf[mi][ni][q] + bv[ni][q & 1];
                        float v = v1[mi][ni][q];
                        v = v + (cc - v) * 0.5f;
                        s[q] = (v >= 1.0f) ? 1.0f : 0.0f;
                        v1[mi][ni][q] = v * (1.0f - s[q]);
                    }
                    *reinterpret_cast<__half2*>(&sout[(long)row0 * kH + col]) =
                        __floats2half2_rn(s[0], s[1]);
                    *reinterpret_cast<__half2*>(&sout[(long)(row0 + 8) * kH + col]) =
                        __floats2half2_rn(s[2], s[3]);
                }
            }
            __threadfence();
            __syncthreads();
            if (L.tid == 0) atomicAdd(&g_flag1[st], 1);
        }
    }
}

// L2/L3: chunks 0-31 of each step = hi (fp32 acc); 32-63 = lo (fp16 acc, folded
// to fp32 every ks). A gated per step by wfl; arrive afl; write spikes or output.
__device__ __forceinline__ void run_l23(uint32_t sbase, int m0, int n0,
                                        const __half* __restrict__ Aall,
                                        const __half* __restrict__ Wc,
                                        const float* __restrict__ bias,
                                        volatile int* wfl, int* afl,
                                        __half* __restrict__ soutall,
                                        float* __restrict__ outf, int N) {
    constexpr uint32_t kABytes = 64 * 128, kStage = kABytes + 16384;
    const Lane L = mk_lane();

    float accf[2][4][4], vst[2][4][4];
#pragma unroll
    for (int i = 0; i < 2; i++)
#pragma unroll
        for (int j = 0; j < 4; j++)
#pragma unroll
            for (int q = 0; q < 4; q++) { accf[i][j][q] = 0.0f; vst[i][j][q] = 0.0f; }

    float bv[4][2];
#pragma unroll
    for (int ni = 0; ni < 4; ni++) {
        int col = n0 + L.wn + ni * 8 + L.tg * 2;
        bv[ni][0] = (col < N) ? bias[col] : 0.0f;
        bv[ni][1] = (col + 1 < N) ? bias[col + 1] : 0.0f;
    }

    auto load_chunk = [&](int gc, int b) {
        const int t = gc >> 6;
        const int ak = (gc & 31) * 64;      // A wraps mod 2048
        const int k0 = (gc & 63) * 64;
        const __half* At = Aall + (size_t)t * kB * kH;
        const uint32_t abuf = sbase + (uint32_t)b * kStage, wbuf = abuf + kABytes;
#pragma unroll
        for (int p = 0; p < 2; p++) {
            int off = (p * 256 + L.tid) * 16;
            cp16(abuf + sw128((uint32_t)off),
                 At + (long)(m0 + (off >> 7)) * kH + ak + ((off & 127) >> 1));
        }
#pragma unroll
        for (int p = 0; p < 4; p++) {
            int off = (p * 256 + L.tid) * 16;
            cp16(wbuf + sw128((uint32_t)off),
                 Wc + (long)(n0 + (off >> 7)) * kK2 + k0 + ((off & 127) >> 1));
        }
        cp_commit();
    };

    wait_flag(&wfl[0], 256);
    load_chunk(0, 0); load_chunk(1, 1);

    for (int gc = 0; gc < kNC23; gc++) {
        const int b = gc % 3;
        if (gc + 1 < kNC23) cp_wait1(); else cp_wait0();
        __syncthreads();
        if (gc + 2 < kNC23) {
            if (((gc + 2) & 63) == 0) wait_flag(&wfl[(gc + 2) >> 6], 256);
            load_chunk(gc + 2, (gc + 2) % 3);
        }

        const uint32_t abuf = sbase + (uint32_t)b * kStage, wbuf = abuf + kABytes;
        const bool lo = (gc & 63) >= 32;   // uniform across CTA
#pragma unroll
        for (int ks = 0; ks < 4; ks++) {
            uint32_t af[2][4], bfr[2][4];
#pragma unroll
            for (int mi = 0; mi < 2; mi++) {
                uint32_t off = (uint32_t)((L.wm + mi * 16 + L.a_r) * 128 + ks * 32 + L.a_k);
                ldmx4(af[mi][0], af[mi][1], af[mi][2], af[mi][3], abuf + sw128(off));
            }
#pragma unroll
            for (int np = 0; np < 2; np++) {
                uint32_t off = (uint32_t)((L.wn + np * 16 + L.b_r) * 128 + ks * 32 + L.b_k);
                ldmx4(bfr[np][0], bfr[np][1], bfr[np][2], bfr[np][3], wbuf + sw128(off));
            }
            if (!lo) {
#pragma unroll
                for (int mi = 0; mi < 2; mi++)
#pragma unroll
                    for (int ni = 0; ni < 4; ni++) {
                        const uint32_t* bp = &bfr[ni >> 1][(ni & 1) * 2];
                        mma16816(accf[mi][ni][0], accf[mi][ni][1], accf[mi][ni][2], accf[mi][ni][3],
                                 af[mi][0], af[mi][1], af[mi][2], af[mi][3], bp[0], bp[1]);
                    }
            } else {
                // lo half: fp16-accumulate this 16-K slab, fold to fp32 immediately
#pragma unroll
                for (int mi = 0; mi < 2; mi++)
#pragma unroll
                    for (int ni = 0; ni < 4; ni++) {
                        const uint32_t* bp = &bfr[ni >> 1][(ni & 1) * 2];
                        uint32_t h0 = 0u, h1 = 0u;
                        mma16816h(h0, h1,
                                  af[mi][0], af[mi][1], af[mi][2], af[mi][3], bp[0], bp[1]);
                        float2 f0 = __half22float2(*reinterpret_cast<__half2*>(&h0));
                        float2 f1 = __half22float2(*reinterpret_cast<__half2*>(&h1));
                        accf[mi][ni][0] += f0.x; accf[mi][ni][1] += f0.y;
                        accf[mi][ni][2] += f1.x; accf[mi][ni][3] += f1.y;
                    }
            }
        }

        if ((gc & 63) == 63) {
            const int st = gc >> 6;
            __half* sout = soutall ? soutall + (size_t)st * kB * N : nullptr;
            const bool wfinal = (outf != nullptr) && (st == kT - 1);
#pragma unroll
            for (int mi = 0; mi < 2; mi++) {
                int row0 = m0 + L.wm + mi * 16 + L.g;
#pragma unroll
                for (int ni = 0; ni < 4; ni++) {
                    int col = n0 + L.wn + ni * 8 + L.tg * 2;
                    float s[4];
#pragma unroll
                    for (int q = 0; q < 4; q++) {
                        float cc = accf[mi][ni][q] + bv[ni][q & 1];
                        float v = vst[mi][ni][q];
                        v = v + (cc - v) * 0.5f;
                        s[q] = (v >= 1.0f) ? 1.0f : 0.0f;
                        vst[mi][ni][q] = v * (1.0f - s[q]);
                        accf[mi][ni][q] = 0.0f;
                    }
                    if (sout) {
                        *reinterpret_cast<__half2*>(&sout[(long)row0 * N + col]) =
                            __floats2half2_rn(s[0], s[1]);
                        *reinterpret_cast<__half2*>(&sout[(long)(row0 + 8) * N + col]) =
                            __floats2half2_rn(s[2], s[3]);
                    }
                    if (wfinal) {
                        if (col < N)     outf[(long)row0 * N + col] = s[0];
                        if (col + 1 < N) outf[(long)row0 * N + col + 1] = s[1];
                        if (col < N)     outf[(long)(row0 + 8) * N + col] = s[2];
                        if (col + 1 < N) outf[(long)(row0 + 8) * N + col + 1] = s[3];
                    }
                }
            }
            if (afl) {
                __threadfence();
                __syncthreads();
                if (L.tid == 0) atomicAdd(&afl[st], 1);
            }
        }
    }
}

// ---------------- the persistent whole-network kernel ----------------
__global__ __launch_bounds__(256, 2) void snn_net(
    const float* __restrict__ b1,
    const float* __restrict__ b2,
    const float* __restrict__ b3,
    float* __restrict__ out)
{
    extern __shared__ __align__(1024) char smem[];
    const uint32_t sbase = smem_u32(smem);
    const int bid = blockIdx.x;

    if (bid < 256) {
        run_l1(sbase, (bid & 15) * 64, (bid >> 4) * 128, b1);
    } else if (bid < 512) {
        const int r = bid - 256;
        run_l23(sbase, (r & 15) * 64, (r >> 4) * 128,
                g_s1all, g_W2c, b2, g_flag1, g_flag2, g_s2all, nullptr, kH);
    } else {
        const int r = bid - 512;
        run_l23(sbase, (r & 15) * 64, (r >> 4) * 128,
                g_s2all, g_W3c, b3, g_flag2, nullptr, nullptr, out, kO);
    }
}

// ---------------- launch ----------------
extern "C" void kernel_launch(void* const* d_in, const int* in_sizes, int n_in,
                              void* d_out, int out_size) {
    const float* x  = (const float*)d_in[0];
    const float* W1 = (const float*)d_in[1];
    const float* b1 = (const float*)d_in[2];
    const float* W2 = (const float*)d_in[3];
    const float* b2 = (const float*)d_in[4];
    const float* W3 = (const float*)d_in[5];
    const float* b3 = (const float*)d_in[6];
    float* out = (float*)d_out;

    cudaFuncSetAttribute(snn_net, cudaFuncAttributeMaxDynamicSharedMemorySize, kSmem);

    build_xcat<<<(int)(((long)kB * kLd1 + 255) / 256), 256>>>(x);
    build_w1<<<dim3(125, 64), 256>>>(W1);
    build_w2<<<dim3(64, 64), 256>>>(W2);
    build_w3<<<dim3(64, 32), 256>>>(W3);

    // whole network: one persistent pipelined launch (256 L1 + 256 L2 + 128 L3)
    snn_net<<<640, 256, kSmem>>>(b1, b2, b3, out);
}

// round 17
// speedup vs baseline: 1.2464x; 1.2464x over previous
#include <cuda_runtime.h>
#include <cuda_fp16.h>
#include <cstdint>

// SNNModel: 3-layer LIF SNN, T=10. B=1024, D=4000, H=2048, O=1000.
// R17: R15 design (persistent pipelined fp32-acc HMMA, proven 1082us) with all
// precompute (xcat, w1+pad, w2, w3, flag init) fused into ONE launch.
//   L1: x=xh+xl, W1=wh+wl; terms xh*wh, xh*wl, xl*wh; K'=1216/step.
//   L2/L3: spikes exact in fp16; W = Wh|Wl K-concat (K'=4096/step).
// Persistent kernel: 640 CTAs (256 L1 | 256 L2 | 128 L3), BM=64, 2 CTAs/SM,
// per-step producer/consumer flags (threadfence+atomicAdd / volatile poll).

namespace {
constexpr int kB = 1024, kD = 4000, kH = 2048, kO = 1000, kT = 10;
constexpr int kK1  = 1216;          // L1 per-step K' (3*400 + 16 pad) = 19 chunks
constexpr int kLd1 = kT * kK1;      // 12160
constexpr int kNC1 = kLd1 / 64;     // 190
constexpr int kK2  = 2 * kH;        // 4096
constexpr int kNC23 = kT * 64;      // 640 chunks per L2/L3 CTA
constexpr unsigned kSmem = 3u * (64u * 128u + 16384u);   // 73728

// fused-build grid sections
constexpr int kGx = (kB * kLd1) / 256;      // 48640 xcat blocks
constexpr int kGw1 = 125 * 64;              // 8000
constexpr int kGw2 = 64 * 64;               // 4096
constexpr int kGw3 = 64 * 32;               // 2048
constexpr int kGbuild = kGx + kGw1 + kGw2 + kGw3;   // 62784
}

// ---------------- persistent device buffers ----------------
__device__ __align__(16) __half g_s1all[(size_t)kT * kB * kH];
__device__ __align__(16) __half g_s2all[(size_t)kT * kB * kH];
__device__ __align__(16) __half g_A1c[(size_t)kB * kLd1];
__device__ __align__(16) __half g_W1c[(size_t)kH * kLd1];
__device__ __align__(16) __half g_W2c[(size_t)kH * kK2];
__device__ __align__(16) __half g_W3c[(size_t)1024 * kK2];
__device__ int g_flag1[kT];   // s1(t) complete: 256 arrivals
__device__ int g_flag2[kT];   // s2(t) complete: 256 arrivals

// ---------------- PTX helpers ----------------
__device__ __forceinline__ uint32_t smem_u32(const void* p) {
    uint32_t a;
    asm("{ .reg .u64 t; cvta.to.shared.u64 t, %1; cvt.u32.u64 %0, t; }" : "=r"(a) : "l"(p));
    return a;
}
__device__ __forceinline__ void cp16(uint32_t dst, const void* src) {
    asm volatile("cp.async.cg.shared.global [%0], [%1], 16;" :: "r"(dst), "l"(src));
}
__device__ __forceinline__ void cp_commit() { asm volatile("cp.async.commit_group;" ::: "memory"); }
__device__ __forceinline__ void cp_wait1()  { asm volatile("cp.async.wait_group 1;" ::: "memory"); }
__device__ __forceinline__ void cp_wait0()  { asm volatile("cp.async.wait_group 0;" ::: "memory"); }
__device__ __forceinline__ void ldmx4(uint32_t& r0, uint32_t& r1, uint32_t& r2, uint32_t& r3,
                                      uint32_t addr) {
    asm volatile("ldmatrix.sync.aligned.m8n8.x4.shared.b16 {%0,%1,%2,%3}, [%4];"
                 : "=r"(r0), "=r"(r1), "=r"(r2), "=r"(r3) : "r"(addr));
}
__device__ __forceinline__ void mma16816(float& c0, float& c1, float& c2, float& c3,
                                         uint32_t a0, uint32_t a1, uint32_t a2, uint32_t a3,
                                         uint32_t b0, uint32_t b1) {
    asm volatile(
        "mma.sync.aligned.m16n8k16.row.col.f32.f16.f16.f32 "
        "{%0,%1,%2,%3}, {%4,%5,%6,%7}, {%8,%9}, {%0,%1,%2,%3};"
        : "+f"(c0), "+f"(c1), "+f"(c2), "+f"(c3)
        : "r"(a0), "r"(a1), "r"(a2), "r"(a3), "r"(b0), "r"(b1));
}
__device__ __forceinline__ uint32_t sw128(uint32_t off) {
    return off ^ ((off >> 3) & 0x70);
}
__device__ __forceinline__ void wait_flag(volatile int* f, int target) {
    while (*f < target) __nanosleep(64);
    __threadfence();   // acquire
}

// ---------------- fused precompute kernel ----------------
// Sections by blockIdx.x: [0,kGx) xcat+flags, [kGx,+kGw1) w1, then w2, then w3.
__global__ void build_all(const float* __restrict__ x,
                          const float* __restrict__ W1,
                          const float* __restrict__ W2,
                          const float* __restrict__ W3) {
    __shared__ float tile[32][33];
    const int bid = blockIdx.x;

    if (bid < kGx) {
        // ---- A1c[m, t*1216 + j] : [xh(400) | xh(400) | xl(400) | pad16] ----
        if (bid == 0 && threadIdx.x < kT) {
            g_flag1[threadIdx.x] = 0; g_flag2[threadIdx.x] = 0;
        }
        long idx = (long)bid * 256 + threadIdx.x;
        int m = (int)(idx / kLd1), c = (int)(idx % kLd1);
        int t = c / kK1, j = c % kK1;
        __half o = __float2half_rn(0.0f);
        if (j < 1200) {
            int seg = j / 400, kk = j % 400;
            float xv = x[(long)m * kD + t * 400 + kk];
            __half h = __float2half_rn(xv);
            o = (seg < 2) ? h : __float2half_rn(xv - __half2float(h));
        }
        g_A1c[idx] = o;
        return;
    }

    const int tx = threadIdx.x & 31, ty = threadIdx.x >> 5;

    if (bid < kGx + kGw1) {
        // ---- W1c per step block: [wh(400) | wl(400) | wh(400) | pad16] ----
        const int r = bid - kGx;
        const int k0 = (r % 125) * 32, n0 = (r / 125) * 32;
        for (int i = 0; i < 32; i += 8)
            tile[ty + i][tx] = W1[(long)(k0 + ty + i) * kH + n0 + tx];
        __syncthreads();
        for (int i = 0; i < 32; i += 8) {
            int n = n0 + ty + i, kg = k0 + tx;
            int t = kg / 400, kk = kg % 400;
            float v = tile[tx][ty + i];
            __half h = __float2half_rn(v);
            __half l = __float2half_rn(v - __half2float(h));
            long base = (long)n * kLd1 + (long)t * kK1;
            g_W1c[base + kk]       = h;
            g_W1c[base + 400 + kk] = l;
            g_W1c[base + 800 + kk] = h;
            if (kk >= 384)   // 16 threads per (n,t): zero pad cols [1200,1216)
                g_W1c[base + 1200 + (kk - 384)] = __float2half_rn(0.0f);
        }
        return;
    }

    if (bid < kGx + kGw1 + kGw2) {
        // ---- W2c: [2048,2048] -> [2048][4096] = Wh | Wl ----
        const int r = bid - kGx - kGw1;
        const int k0 = (r & 63) * 32, n0 = (r >> 6) * 32;
        for (int i = 0; i < 32; i += 8)
            tile[ty + i][tx] = W2[(long)(k0 + ty + i) * kH + n0 + tx];
        __syncthreads();
        for (int i = 0; i < 32; i += 8) {
            int n = n0 + ty + i, k = k0 + tx;
            float v = tile[tx][ty + i];
            __half h = __float2half_rn(v);
            __half l = __float2half_rn(v - __half2float(h));
            long base = (long)n * kK2;
            g_W2c[base + k] = h; g_W2c[base + kH + k] = l;
        }
        return;
    }

    {
        // ---- W3c: [2048,1000] -> [1024][4096] = Wh | Wl (N padded) ----
        const int r = bid - kGx - kGw1 - kGw2;
        const int k0 = (r & 63) * 32, n0 = (r >> 6) * 32;
        for (int i = 0; i < 32; i += 8) {
            int n = n0 + tx;
            tile[ty + i][tx] = (n < kO) ? W3[(long)(k0 + ty + i) * kO + n] : 0.0f;
        }
        __syncthreads();
        for (int i = 0; i < 32; i += 8) {
            int n = n0 + ty + i, k = k0 + tx;
            float v = tile[tx][ty + i];
            __half h = __float2half_rn(v);
            __half l = __float2half_rn(v - __half2float(h));
            long base = (long)n * kK2;
            g_W3c[base + k] = h; g_W3c[base + kH + k] = l;
        }
    }
}

// ---------------- role bodies ----------------
struct Lane {
    int tid, wid, lid, wm, wn, g, tg, a_r, a_k, b_r, b_k;
};
__device__ __forceinline__ Lane mk_lane() {
    Lane L;
    L.tid = threadIdx.x; L.wid = L.tid >> 5; L.lid = L.tid & 31;
    L.wm = (L.wid >> 2) * 32; L.wn = (L.wid & 3) * 32;
    L.g = L.lid >> 2; L.tg = L.lid & 3;
    L.a_r = (L.lid & 7) + ((L.lid >> 3) & 1) * 8; L.a_k = (L.lid >> 4) * 16;
    L.b_r = (L.lid & 7) + (L.lid >> 4) * 8;       L.b_k = ((L.lid >> 3) & 1) * 16;
    return L;
}

// L1: 190 chunks, fp32 accumulate, LIF at c%19==18, arrive g_flag1.
__device__ __forceinline__ void run_l1(uint32_t sbase, int m0, int n0,
                                       const float* __restrict__ bias) {
    constexpr uint32_t kABytes = 64 * 128, kStage = kABytes + 16384;
    const Lane L = mk_lane();

    float accf[2][4][4], v1[2][4][4];
#pragma unroll
    for (int i = 0; i < 2; i++)
#pragma unroll
        for (int j = 0; j < 4; j++)
#pragma unroll
            for (int q = 0; q < 4; q++) { accf[i][j][q] = 0.0f; v1[i][j][q] = 0.0f; }

    float bv[4][2];
#pragma unroll
    for (int ni = 0; ni < 4; ni++) {
        int col = n0 + L.wn + ni * 8 + L.tg * 2;
        bv[ni][0] = bias[col]; bv[ni][1] = bias[col + 1];
    }

    auto load_chunk = [&](int c, int b) {
        const int k0 = c * 64;
        const uint32_t abuf = sbase + (uint32_t)b * kStage, wbuf = abuf + kABytes;
#pragma unroll
        for (int p = 0; p < 2; p++) {
            int off = (p * 256 + L.tid) * 16;
            cp16(abuf + sw128((uint32_t)off),
                 g_A1c + (long)(m0 + (off >> 7)) * kLd1 + k0 + ((off & 127) >> 1));
        }
#pragma unroll
        for (int p = 0; p < 4; p++) {
            int off = (p * 256 + L.tid) * 16;
            cp16(wbuf + sw128((uint32_t)off),
                 g_W1c + (long)(n0 + (off >> 7)) * kLd1 + k0 + ((off & 127) >> 1));
        }
        cp_commit();
    };

    load_chunk(0, 0); load_chunk(1, 1);

    for (int c = 0; c < kNC1; c++) {
        const int b = c % 3;
        if (c + 1 < kNC1) cp_wait1(); else cp_wait0();
        __syncthreads();
        if (c + 2 < kNC1) load_chunk(c + 2, (c + 2) % 3);

        const uint32_t abuf = sbase + (uint32_t)b * kStage, wbuf = abuf + kABytes;
#pragma unroll
        for (int ks = 0; ks < 4; ks++) {
            uint32_t af[2][4], bfr[2][4];
#pragma unroll
            for (int mi = 0; mi < 2; mi++) {
                uint32_t off = (uint32_t)((L.wm + mi * 16 + L.a_r) * 128 + ks * 32 + L.a_k);
                ldmx4(af[mi][0], af[mi][1], af[mi][2], af[mi][3], abuf + sw128(off));
            }
#pragma unroll
            for (int np = 0; np < 2; np++) {
                uint32_t off = (uint32_t)((L.wn + np * 16 + L.b_r) * 128 + ks * 32 + L.b_k);
                ldmx4(bfr[np][0], bfr[np][1], bfr[np][2], bfr[np][3], wbuf + sw128(off));
            }
#pragma unroll
            for (int mi = 0; mi < 2; mi++)
#pragma unroll
                for (int ni = 0; ni < 4; ni++) {
                    const uint32_t* bp = &bfr[ni >> 1][(ni & 1) * 2];
                    mma16816(accf[mi][ni][0], accf[mi][ni][1], accf[mi][ni][2], accf[mi][ni][3],
                             af[mi][0], af[mi][1], af[mi][2], af[mi][3], bp[0], bp[1]);
                }
        }

        if (c % 19 == 18) {
            const int st = c / 19;
            __half* sout = g_s1all + (size_t)st * kB * kH;
#pragma unroll
            for (int mi = 0; mi < 2; mi++) {
                int row0 = m0 + L.wm + mi * 16 + L.g;
#pragma unroll
                for (int ni = 0; ni < 4; ni++) {
                    int col = n0 + L.wn + ni * 8 + L.tg * 2;
                    float s[4];
#pragma unroll
                    for (int q = 0; q < 4; q++) {
                        float cc = accf[mi][ni][q] + bv[ni][q & 1];
                        float v = v1[mi][ni][q];
                        v = v + (cc - v) * 0.5f;
                        s[q] = (v >= 1.0f) ? 1.0f : 0.0f;
                        v1[mi][ni][q] = v * (1.0f - s[q]);
                    }
                    *reinterpret_cast<__half2*>(&sout[(long)row0 * kH + col]) =
                        __floats2half2_rn(s[0], s[1]);
                    *reinterpret_cast<__half2*>(&sout[(long)(row0 + 8) * kH + col]) =
                        __floats2half2_rn(s[2], s[3]);
                }
            }
            __threadfence();
            __syncthreads();
            if (L.tid == 0) atomicAdd(&g_flag1[st], 1);
        }
    }
}

// L2/L3: A from Aall [T,B,2048] gated per step by wfl; W [*,4096]; arrive afl;
// write spikes (soutall) or final float output (outf).
__device__ __forceinline__ void run_l23(uint32_t sbase, int m0, int n0,
                                        const __half* __restrict__ Aall,
                                        const __half* __restrict__ Wc,
                                        const float* __restrict__ bias,
                                        volatile int* wfl, int* afl,
                                        __half* __restrict__ soutall,
                                        float* __restrict__ outf, int N) {
    constexpr uint32_t kABytes = 64 * 128, kStage = kABytes + 16384;
    const Lane L = mk_lane();

    float accf[2][4][4], vst[2][4][4];
#pragma unroll
    for (int i = 0; i < 2; i++)
#pragma unroll
        for (int j = 0; j < 4; j++)
#pragma unroll
            for (int q = 0; q < 4; q++) { accf[i][j][q] = 0.0f; vst[i][j][q] = 0.0f; }

    float bv[4][2];
#pragma unroll
    for (int ni = 0; ni < 4; ni++) {
        int col = n0 + L.wn + ni * 8 + L.tg * 2;
        bv[ni][0] = (col < N) ? bias[col] : 0.0f;
        bv[ni][1] = (col + 1 < N) ? bias[col + 1] : 0.0f;
    }

    auto load_chunk = [&](int gc, int b) {
        const int t = gc >> 6;
        const int ak = (gc & 31) * 64;      // A wraps mod 2048
        const int k0 = (gc & 63) * 64;
        const __half* At = Aall + (size_t)t * kB * kH;
        const uint32_t abuf = sbase + (uint32_t)b * kStage, wbuf = abuf + kABytes;
#pragma unroll
        for (int p = 0; p < 2; p++) {
            int off = (p * 256 + L.tid) * 16;
            cp16(abuf + sw128((uint32_t)off),
                 At + (long)(m0 + (off >> 7)) * kH + ak + ((off & 127) >> 1));
        }
#pragma unroll
        for (int p = 0; p < 4; p++) {
            int off = (p * 256 + L.tid) * 16;
            cp16(wbuf + sw128((uint32_t)off),
                 Wc + (long)(n0 + (off >> 7)) * kK2 + k0 + ((off & 127) >> 1));
        }
        cp_commit();
    };

    wait_flag(&wfl[0], 256);
    load_chunk(0, 0); load_chunk(1, 1);

    for (int gc = 0; gc < kNC23; gc++) {
        const int b = gc % 3;
        if (gc + 1 < kNC23) cp_wait1(); else cp_wait0();
        __syncthreads();
        if (gc + 2 < kNC23) {
            if (((gc + 2) & 63) == 0) wait_flag(&wfl[(gc + 2) >> 6], 256);
            load_chunk(gc + 2, (gc + 2) % 3);
        }

        const uint32_t abuf = sbase + (uint32_t)b * kStage, wbuf = abuf + kABytes;
#pragma unroll
        for (int ks = 0; ks < 4; ks++) {
            uint32_t af[2][4], bfr[2][4];
#pragma unroll
            for (int mi = 0; mi < 2; mi++) {
                uint32_t off = (uint32_t)((L.wm + mi * 16 + L.a_r) * 128 + ks * 32 + L.a_k);
                ldmx4(af[mi][0], af[mi][1], af[mi][2], af[mi][3], abuf + sw128(off));
            }
#pragma unroll
            for (int np = 0; np < 2; np++) {
                uint32_t off = (uint32_t)((L.wn + np * 16 + L.b_r) * 128 + ks * 32 + L.b_k);
                ldmx4(bfr[np][0], bfr[np][1], bfr[np][2], bfr[np][3], wbuf + sw128(off));
            }
#pragma unroll
            for (int mi = 0; mi < 2; mi++)
#pragma unroll
                for (int ni = 0; ni < 4; ni++) {
                    const uint32_t* bp = &bfr[ni >> 1][(ni & 1) * 2];
                    mma16816(accf[mi][ni][0], accf[mi][ni][1], accf[mi][ni][2], accf[mi][ni][3],
                             af[mi][0], af[mi][1], af[mi][2], af[mi][3], bp[0], bp[1]);
                }
        }

        if ((gc & 63) == 63) {
            const int st = gc >> 6;
            __half* sout = soutall ? soutall + (size_t)st * kB * N : nullptr;
            const bool wfinal = (outf != nullptr) && (st == kT - 1);
#pragma unroll
            for (int mi = 0; mi < 2; mi++) {
                int row0 = m0 + L.wm + mi * 16 + L.g;
#pragma unroll
                for (int ni = 0; ni < 4; ni++) {
                    int col = n0 + L.wn + ni * 8 + L.tg * 2;
                    float s[4];
#pragma unroll
                    for (int q = 0; q < 4; q++) {
                        float cc = accf[mi][ni][q] + bv[ni][q & 1];
                        float v = vst[mi][ni][q];
                        v = v + (cc - v) * 0.5f;
                        s[q] = (v >= 1.0f) ? 1.0f : 0.0f;
                        vst[mi][ni][q] = v * (1.0f - s[q]);
                        accf[mi][ni][q] = 0.0f;
                    }
                    if (sout) {
                        *reinterpret_cast<__half2*>(&sout[(long)row0 * N + col]) =
                            __floats2half2_rn(s[0], s[1]);
                        *reinterpret_cast<__half2*>(&sout[(long)(row0 + 8) * N + col]) =
                            __floats2half2_rn(s[2], s[3]);
                    }
                    if (wfinal) {
                        if (col < N)     outf[(long)row0 * N + col] = s[0];
                        if (col + 1 < N) outf[(long)row0 * N + col + 1] = s[1];
                        if (col < N)     outf[(long)(row0 + 8) * N + col] = s[2];
                        if (col + 1 < N) outf[(long)(row0 + 8) * N + col + 1] = s[3];
                    }
                }
            }
            if (afl) {
                __threadfence();
                __syncthreads();
                if (L.tid == 0) atomicAdd(&afl[st], 1);
            }
        }
    }
}

// ---------------- the persistent whole-network kernel ----------------
__global__ __launch_bounds__(256, 2) void snn_net(
    const float* __restrict__ b1,
    const float* __restrict__ b2,
    const float* __restrict__ b3,
    float* __restrict__ out)
{
    extern __shared__ __align__(1024) char smem[];
    const uint32_t sbase = smem_u32(smem);
    const int bid = blockIdx.x;

    if (bid < 256) {
        // layer 1 workers (lowest bids -> resident in wave 1, no deadlock)
        run_l1(sbase, (bid & 15) * 64, (bid >> 4) * 128, b1);
    } else if (bid < 512) {
        const int r = bid - 256;
        run_l23(sbase, (r & 15) * 64, (r >> 4) * 128,
                g_s1all, g_W2c, b2, g_flag1, g_flag2, g_s2all, nullptr, kH);
    } else {
        const int r = bid - 512;
        run_l23(sbase, (r & 15) * 64, (r >> 4) * 128,
                g_s2all, g_W3c, b3, g_flag2, nullptr, nullptr, out, kO);
    }
}

// ---------------- launch ----------------
extern "C" void kernel_launch(void* const* d_in, const int* in_sizes, int n_in,
                              void* d_out, int out_size) {
    const float* x  = (const float*)d_in[0];
    const float* W1 = (const float*)d_in[1];
    const float* b1 = (const float*)d_in[2];
    const float* W2 = (const float*)d_in[3];
    const float* b2 = (const float*)d_in[4];
    const float* W3 = (const float*)d_in[5];
    const float* b3 = (const float*)d_in[6];
    float* out = (float*)d_out;

    cudaFuncSetAttribute(snn_net, cudaFuncAttributeMaxDynamicSharedMemorySize, kSmem);

    // all precompute in one launch
    build_all<<<kGbuild, 256>>>(x, W1, W2, W3);

    // whole network: one persistent pipelined launch (256 L1 + 256 L2 + 128 L3)
    snn_net<<<640, 256, kSmem>>>(b1, b2, b3, out);
}